// round 6
// baseline (speedup 1.0000x reference)
#include <cuda_runtime.h>
#include <cuda_bf16.h>
#include <cstdint>

#define BB 8
#define TT 2048
#define DD 1024
#define HH 4
#define BT (BB*TT)
#define UU 1365
#define UU2 2730
#define AP 1376

// ---- static scratch (allocated at module load; sanctioned workaround) ----
__device__ float g_xn   [(size_t)BT*DD];
__device__ float g_ifin [(size_t)BT*DD];
__device__ float g_linif[(size_t)BT*2048];
__device__ float g_linzo[(size_t)BT*2048];
__device__ float g_hall [(size_t)BT*DD];
__device__ float g_zn   [(size_t)BT*DD];
__device__ float g_up   [(size_t)BT*UU2];
__device__ float g_act  [(size_t)BT*AP];
__device__ float g_dw   [(size_t)DD*AP];
__device__ float g_hstate[2*BB*DD];
__device__ unsigned g_cnt[HH];

// ---------------- init: zero h buffers + counters (runs every launch) ----------
__global__ void init_kernel() {
    int i = blockIdx.x*blockDim.x + threadIdx.x;
    if (i < 2*BB*DD) g_hstate[i] = 0.f;
    if (i < HH) g_cnt[i] = 0u;
}

// ---------------- pad down_w (1024 x 1365) -> g_dw (1024 x 1376) ---------------
__global__ void prep_dw_kernel(const float* __restrict__ dw) {
    int i = blockIdx.x*blockDim.x + threadIdx.x;
    if (i >= DD*AP) return;
    int r = i / AP, c = i - r*AP;
    g_dw[i] = (c < UU) ? dw[(size_t)r*UU + c] : 0.f;
}

// ---------------- LayerNorm per (b,t) row --------------------------------------
__global__ __launch_bounds__(256) void ln_kernel(const float* __restrict__ x,
                                                 const float* __restrict__ w,
                                                 const float* __restrict__ b) {
    int m = blockIdx.x, tid = threadIdx.x;
    const float* row = x + (size_t)m*DD;
    float4 v = *(const float4*)&row[tid*4];
    float s = v.x+v.y+v.z+v.w;
    float ss = v.x*v.x+v.y*v.y+v.z*v.z+v.w*v.w;
    __shared__ float rs[8], rss[8];
    #pragma unroll
    for (int o=16;o>0;o>>=1){ s+=__shfl_down_sync(0xffffffffu,s,o); ss+=__shfl_down_sync(0xffffffffu,ss,o); }
    if ((tid&31)==0){ rs[tid>>5]=s; rss[tid>>5]=ss; }
    __syncthreads();
    float ts=0.f, tss=0.f;
    #pragma unroll
    for (int wp=0;wp<8;wp++){ ts+=rs[wp]; tss+=rss[wp]; }
    float mu = ts*(1.0f/DD);
    float inv = rsqrtf(tss*(1.0f/DD) - mu*mu + 1e-5f);
    int d = tid*4;
    float4 o4;
    o4.x = (v.x-mu)*inv*w[d+0]+b[d+0];
    o4.y = (v.y-mu)*inv*w[d+1]+b[d+1];
    o4.z = (v.z-mu)*inv*w[d+2]+b[d+2];
    o4.w = (v.w-mu)*inv*w[d+3]+b[d+3];
    *(float4*)&g_xn[(size_t)m*DD + d] = o4;
}

// ---------------- causal conv K=4 + swish --------------------------------------
__global__ __launch_bounds__(256) void conv_kernel(const float* __restrict__ cw,
                                                   const float* __restrict__ cb) {
    size_t idx = (size_t)blockIdx.x*blockDim.x + threadIdx.x;  // BT*DD threads
    int d = (int)(idx & (DD-1));
    int t = (int)((idx >> 10) & (TT-1));
    float4 c4 = *(const float4*)&cw[d*4];
    float acc = cb[d] + c4.w * g_xn[idx];
    if (t>=1) acc += c4.z * g_xn[idx-DD];
    if (t>=2) acc += c4.y * g_xn[idx-2*DD];
    if (t>=3) acc += c4.x * g_xn[idx-3*DD];
    g_ifin[idx] = acc / (1.0f + expf(-acc));
}

// ---------------- fp32 GEMM  C[M,N] = A[M,K] @ W[N,K]^T (+ epilogue) -----------
// EPI: 0 none, 1 +bias, 2 +bias+residual
template<int EPI>
__global__ __launch_bounds__(256) void gemm_nt(const float* __restrict__ A,
                                               const float* __restrict__ W,
                                               float* __restrict__ C,
                                               int M, int N, int Kd,
                                               int lda, int ldw, int ldc,
                                               const float* __restrict__ bias,
                                               const float* __restrict__ res) {
    __shared__ float As[16][132];
    __shared__ float Bs[16][132];
    int tid = threadIdx.x;
    int bm = blockIdx.y * 128, bn = blockIdx.x * 128;
    int tx = tid & 15, ty = tid >> 4;
    int r0 = tid >> 2, kq = (tid & 3) << 2;

    const float* Ap0 = A + (size_t)(bm + r0)      * lda + kq;
    const float* Ap1 = A + (size_t)(bm + r0 + 64) * lda + kq;
    int n0 = bn + r0, n1 = bn + r0 + 64;
    const float* Wp0 = W + (size_t)n0 * ldw + kq;
    const float* Wp1 = W + (size_t)n1 * ldw + kq;
    bool wg0 = n0 < N, wg1 = n1 < N;

    float acc[8][8];
    #pragma unroll
    for (int i=0;i<8;i++)
        #pragma unroll
        for (int j=0;j<8;j++) acc[i][j]=0.f;

    int ktiles = Kd >> 4;
    float4 a0 = *(const float4*)Ap0;
    float4 a1 = *(const float4*)Ap1;
    float4 b0 = wg0 ? *(const float4*)Wp0 : make_float4(0,0,0,0);
    float4 b1 = wg1 ? *(const float4*)Wp1 : make_float4(0,0,0,0);

    for (int kt = 0; kt < ktiles; ++kt) {
        As[kq+0][r0]=a0.x; As[kq+1][r0]=a0.y; As[kq+2][r0]=a0.z; As[kq+3][r0]=a0.w;
        As[kq+0][r0+64]=a1.x; As[kq+1][r0+64]=a1.y; As[kq+2][r0+64]=a1.z; As[kq+3][r0+64]=a1.w;
        Bs[kq+0][r0]=b0.x; Bs[kq+1][r0]=b0.y; Bs[kq+2][r0]=b0.z; Bs[kq+3][r0]=b0.w;
        Bs[kq+0][r0+64]=b1.x; Bs[kq+1][r0+64]=b1.y; Bs[kq+2][r0+64]=b1.z; Bs[kq+3][r0+64]=b1.w;
        __syncthreads();
        if (kt+1 < ktiles) {
            int off = (kt+1)*16;
            a0 = *(const float4*)(Ap0 + off);
            a1 = *(const float4*)(Ap1 + off);
            b0 = wg0 ? *(const float4*)(Wp0 + off) : make_float4(0,0,0,0);
            b1 = wg1 ? *(const float4*)(Wp1 + off) : make_float4(0,0,0,0);
        }
        #pragma unroll
        for (int kk=0; kk<16; ++kk) {
            float4 av0 = *(const float4*)&As[kk][4*ty];
            float4 av1 = *(const float4*)&As[kk][64+4*ty];
            float4 bv0 = *(const float4*)&Bs[kk][4*tx];
            float4 bv1 = *(const float4*)&Bs[kk][64+4*tx];
            float av[8] = {av0.x,av0.y,av0.z,av0.w, av1.x,av1.y,av1.z,av1.w};
            float bv[8] = {bv0.x,bv0.y,bv0.z,bv0.w, bv1.x,bv1.y,bv1.z,bv1.w};
            #pragma unroll
            for (int i=0;i<8;i++)
                #pragma unroll
                for (int j=0;j<8;j++) acc[i][j] += av[i]*bv[j];
        }
        __syncthreads();
    }
    #pragma unroll
    for (int i=0;i<8;i++) {
        int m = bm + ((i<4) ? 4*ty+i : 64+4*ty+(i-4));
        #pragma unroll
        for (int j=0;j<8;j++) {
            int n = bn + ((j<4) ? 4*tx+j : 64+4*tx+(j-4));
            if (n < N) {
                float v = acc[i][j];
                if (EPI >= 1) v += bias[n];
                if (EPI == 2) v += res[(size_t)m*ldc + n];
                C[(size_t)m*ldc + n] = v;
            }
        }
    }
}

// ---------------- sequential sLSTM recurrence ----------------------------------
// 32 CTAs: head = blk>>3, j = blk&7. CTA owns s in [j*32,j*32+32) for 4 gates,
// 8 batches. W_hh slice (128x256 fp32) resident in SMEM. h exchanged via L2.
__global__ __launch_bounds__(256) void recur_kernel(const float* __restrict__ w_hh,
                                                    const float* __restrict__ bias) {
    extern __shared__ float sm[];
    float* Wsm    = sm;                 // 128 * 260
    float* h_sm   = Wsm + 128*260;      // 8 * 256
    float* lin_sm = h_sm + 2048;        // 128 * 8

    int tid  = threadIdx.x;
    int head = blockIdx.x >> 3;
    int j    = blockIdx.x & 7;
    int r  = tid & 127;                 // row: g*32 + sl
    int bg = tid >> 7;                  // batch group (0/1 -> batches bg*4..+3)
    int g  = r >> 5, sl = r & 31;

    // stage weights (one-time)
    #pragma unroll
    for (int it = 0; it < 32; ++it) {
        int idx4 = tid + it*256;
        int rl = idx4 >> 6;
        int k4 = (idx4 & 63) << 2;
        int gg = rl >> 5, ssl = rl & 31;
        float4 wv = *(const float4*)&w_hh[((size_t)(head*1024 + gg*256 + j*32 + ssl))*256 + k4];
        *(float4*)&Wsm[rl*260 + k4] = wv;
    }

    float bias_v = bias[head*1024 + g*256 + j*32 + sl];
    const float* linp = (g < 2) ? g_linif : g_linzo;
    size_t colOff = (size_t)head*512 + (size_t)(g & 1)*256 + j*32 + sl;

    // gate-phase: fixed (s,b) per thread, state in registers
    int gs = tid & 31;
    int gb = tid >> 5;
    float c_st = 0.f, m_st = 0.f, n_st = 0.f;
    __syncthreads();

    int p = 0;
    for (int t = 0; t < TT; ++t) {
        float l0 = linp[((size_t)(bg*4+0)*TT + t)*2048 + colOff];
        float l1 = linp[((size_t)(bg*4+1)*TT + t)*2048 + colOff];
        float l2 = linp[((size_t)(bg*4+2)*TT + t)*2048 + colOff];
        float l3 = linp[((size_t)(bg*4+3)*TT + t)*2048 + colOff];

        const float* hp = g_hstate + p*BB*DD;
        #pragma unroll
        for (int it = 0; it < 2; ++it) {
            int f4 = tid + it*256;
            int bb = f4 >> 6;
            int kk = (f4 & 63) << 2;
            float4 hv = __ldcg((const float4*)&hp[bb*DD + head*256 + kk]);
            *(float4*)&h_sm[bb*256 + kk] = hv;
        }
        __syncthreads();

        float a0 = l0 + bias_v, a1 = l1 + bias_v, a2 = l2 + bias_v, a3 = l3 + bias_v;
        const float* w  = &Wsm[r*260];
        const float* hA = &h_sm[(bg*4)*256];
        #pragma unroll 8
        for (int k = 0; k < 256; k += 4) {
            float4 wv = *(const float4*)(w+k);
            float4 x0 = *(const float4*)(hA + k);
            float4 x1 = *(const float4*)(hA + 256 + k);
            float4 x2 = *(const float4*)(hA + 512 + k);
            float4 x3 = *(const float4*)(hA + 768 + k);
            a0 += wv.x*x0.x + wv.y*x0.y + wv.z*x0.z + wv.w*x0.w;
            a1 += wv.x*x1.x + wv.y*x1.y + wv.z*x1.z + wv.w*x1.w;
            a2 += wv.x*x2.x + wv.y*x2.y + wv.z*x2.z + wv.w*x2.w;
            a3 += wv.x*x3.x + wv.y*x3.y + wv.z*x3.z + wv.w*x3.w;
        }
        lin_sm[r*8 + bg*4 + 0] = a0;
        lin_sm[r*8 + bg*4 + 1] = a1;
        lin_sm[r*8 + bg*4 + 2] = a2;
        lin_sm[r*8 + bg*4 + 3] = a3;
        __syncthreads();

        // gate math for (gs, gb)
        float iv = lin_sm[gs*8 + gb];
        float fv = lin_sm[(32+gs)*8 + gb];
        float zv = tanhf(lin_sm[(64+gs)*8 + gb]);
        float ov = 1.0f/(1.0f + expf(-lin_sm[(96+gs)*8 + gb]));
        float mn = fmaxf(fv + m_st, iv);
        float ie = expf(iv - mn);
        float fe = expf(fv + m_st - mn);
        c_st = fe*c_st + ie*zv;
        n_st = fe*n_st + ie;
        m_st = mn;
        float hn = ov * (c_st / n_st);
        int sg = j*32 + gs;
        __stcg(&g_hstate[(p^1)*BB*DD + gb*DD + head*256 + sg], hn);
        g_hall[((size_t)gb*TT + t)*DD + head*256 + sg] = hn;

        __threadfence();
        __syncthreads();
        if (tid == 0) {
            atomicAdd(&g_cnt[head], 1u);
            volatile unsigned* cv = &g_cnt[head];
            unsigned tgt = 8u*(unsigned)(t+1);
            while (*cv < tgt) {}
            __threadfence();
        }
        __syncthreads();
        p ^= 1;
    }
}

// ---------------- GroupNorm (per head of 256) ----------------------------------
__global__ __launch_bounds__(256) void gn_kernel(const float* __restrict__ w,
                                                 const float* __restrict__ b) {
    int m = blockIdx.x, tid = threadIdx.x;
    const float* row = g_hall + (size_t)m*DD;
    float4 v = *(const float4*)&row[tid*4];
    float s = v.x+v.y+v.z+v.w;
    float ss = v.x*v.x+v.y*v.y+v.z*v.z+v.w*v.w;
    __shared__ float ws[8], wss[8];
    #pragma unroll
    for (int o=16;o>0;o>>=1){ s+=__shfl_down_sync(0xffffffffu,s,o); ss+=__shfl_down_sync(0xffffffffu,ss,o); }
    if ((tid&31)==0){ ws[tid>>5]=s; wss[tid>>5]=ss; }
    __syncthreads();
    int h = tid >> 6;                          // 64 threads per head
    float hs  = ws[2*h]  + ws[2*h+1];
    float hss = wss[2*h] + wss[2*h+1];
    float mu = hs*(1.0f/256.0f);
    float inv = rsqrtf(hss*(1.0f/256.0f) - mu*mu + 1e-5f);
    int d = tid*4;
    float4 o4;
    o4.x = (v.x-mu)*inv*w[d+0]+b[d+0];
    o4.y = (v.y-mu)*inv*w[d+1]+b[d+1];
    o4.z = (v.z-mu)*inv*w[d+2]+b[d+2];
    o4.w = (v.w-mu)*inv*w[d+3]+b[d+3];
    *(float4*)&g_zn[(size_t)m*DD + d] = o4;
}

// ---------------- gelu(u1)*u2 into K-padded g_act ------------------------------
__global__ __launch_bounds__(256) void act_kernel() {
    int m = blockIdx.x;
    const float* up = g_up + (size_t)m*UU2;
    float* dst = g_act + (size_t)m*AP;
    for (int c = threadIdx.x; c < AP; c += 256) {
        float v = 0.f;
        if (c < UU) {
            float u1 = up[c], u2 = up[UU + c];
            float gl = 0.5f*u1*(1.0f + tanhf(0.7978845608028654f*(u1 + 0.044715f*u1*u1*u1)));
            v = gl * u2;
        }
        dst[c] = v;
    }
}

// ---------------- launch -------------------------------------------------------
extern "C" void kernel_launch(void* const* d_in, const int* in_sizes, int n_in,
                              void* d_out, int out_size) {
    const float* x      = (const float*)d_in[0];
    const float* ln_w   = (const float*)d_in[1];
    const float* ln_b   = (const float*)d_in[2];
    const float* conv_w = (const float*)d_in[3];
    const float* conv_b = (const float*)d_in[4];
    const float* w_if   = (const float*)d_in[5];
    const float* w_zo   = (const float*)d_in[6];
    const float* w_hh   = (const float*)d_in[7];
    const float* bias   = (const float*)d_in[8];
    const float* gn_w   = (const float*)d_in[9];
    const float* gn_b   = (const float*)d_in[10];
    const float* up_w   = (const float*)d_in[11];
    const float* up_b   = (const float*)d_in[12];
    const float* dn_w   = (const float*)d_in[13];
    const float* dn_b   = (const float*)d_in[14];
    float* out = (float*)d_out;

    float *p_xn, *p_ifin, *p_linif, *p_linzo, *p_zn, *p_up, *p_act, *p_dw;
    cudaGetSymbolAddress((void**)&p_xn,    g_xn);
    cudaGetSymbolAddress((void**)&p_ifin,  g_ifin);
    cudaGetSymbolAddress((void**)&p_linif, g_linif);
    cudaGetSymbolAddress((void**)&p_linzo, g_linzo);
    cudaGetSymbolAddress((void**)&p_zn,    g_zn);
    cudaGetSymbolAddress((void**)&p_up,    g_up);
    cudaGetSymbolAddress((void**)&p_act,   g_act);
    cudaGetSymbolAddress((void**)&p_dw,    g_dw);

    const int RECUR_SMEM = (128*260 + 2048 + 1024) * 4;  // 145408 B
    cudaFuncSetAttribute(recur_kernel, cudaFuncAttributeMaxDynamicSharedMemorySize, RECUR_SMEM);

    init_kernel<<<64, 256>>>();
    prep_dw_kernel<<<(DD*AP + 255)/256, 256>>>(dn_w);
    ln_kernel<<<BT, 256>>>(x, ln_w, ln_b);
    conv_kernel<<<(int)(((size_t)BT*DD)/256), 256>>>(conv_w, conv_b);

    dim3 gLin(16, 128);
    gemm_nt<0><<<gLin, 256>>>(p_ifin, w_if, p_linif, BT, 2048, 1024, 1024, 1024, 2048, nullptr, nullptr);
    gemm_nt<0><<<gLin, 256>>>(p_xn,   w_zo, p_linzo, BT, 2048, 1024, 1024, 1024, 2048, nullptr, nullptr);

    recur_kernel<<<32, 256, RECUR_SMEM>>>(w_hh, bias);

    gn_kernel<<<BT, 256>>>(gn_w, gn_b);

    dim3 gUp(22, 128);
    gemm_nt<1><<<gUp, 256>>>(p_zn, up_w, p_up, BT, UU2, 1024, 1024, 1024, UU2, up_b, nullptr);

    act_kernel<<<BT, 256>>>();

    dim3 gDn(8, 128);
    gemm_nt<2><<<gDn, 256>>>(p_act, p_dw, out, BT, 1024, AP, AP, AP, 1024, dn_b, x);
}

// round 12
// speedup vs baseline: 1.6543x; 1.6543x over previous
#include <cuda_runtime.h>
#include <cuda_bf16.h>
#include <cstdint>

#define BB 8
#define TT 2048
#define DD 1024
#define HH 4
#define BT (BB*TT)
#define UU 1365
#define UPAD 2816     // padded 2*U (22 tiles of 128)
#define KDN 1408      // padded K for down GEMM (22 chunks of 64)

typedef __nv_bfloat16 bf16;

// ------------------------- static scratch --------------------------------------
__device__ bf16  g_xn_h [(size_t)BT*DD];
__device__ bf16  g_xn_l [(size_t)BT*DD];
__device__ bf16  g_if_h [(size_t)BT*DD];
__device__ bf16  g_if_l [(size_t)BT*DD];
__device__ float g_linif[(size_t)BT*2048];
__device__ float g_linzo[(size_t)BT*2048];
__device__ float g_hall [(size_t)BT*DD];
__device__ bf16  g_zn_h [(size_t)BT*DD];
__device__ bf16  g_zn_l [(size_t)BT*DD];
__device__ float g_up   [(size_t)BT*UPAD];
__device__ bf16  g_act_h[(size_t)BT*KDN];
__device__ bf16  g_act_l[(size_t)BT*KDN];
__device__ bf16  g_wif_h[2048*1024];
__device__ bf16  g_wif_l[2048*1024];
__device__ bf16  g_wzo_h[2048*1024];
__device__ bf16  g_wzo_l[2048*1024];
__device__ bf16  g_wup_h[(size_t)UPAD*1024];
__device__ bf16  g_wup_l[(size_t)UPAD*1024];
__device__ bf16  g_wdn_h[(size_t)1024*KDN];
__device__ bf16  g_wdn_l[(size_t)1024*KDN];
__device__ float g_upb  [UPAD];
__device__ float g_hstate[2*BB*DD];
__device__ unsigned g_cnt[8];

// ------------------------- helpers ---------------------------------------------
__device__ __forceinline__ uint32_t sw128(uint32_t off) { return off ^ ((off >> 3) & 0x70); }

__device__ __forceinline__ void cp_async16(uint32_t dst, const void* src) {
    asm volatile("cp.async.cg.shared.global [%0], [%1], 16;\n" :: "r"(dst), "l"(src));
}
__device__ __forceinline__ void cp_commit() { asm volatile("cp.async.commit_group;" ::: "memory"); }
template<int N>
__device__ __forceinline__ void cp_wait() { asm volatile("cp.async.wait_group %0;" :: "n"(N) : "memory"); }

__device__ __forceinline__ void ldm_x4(uint32_t* r, uint32_t addr) {
    asm volatile("ldmatrix.sync.aligned.m8n8.x4.shared.b16 {%0,%1,%2,%3}, [%4];"
        : "=r"(r[0]), "=r"(r[1]), "=r"(r[2]), "=r"(r[3]) : "r"(addr));
}
__device__ __forceinline__ void mma_bf16(float* d, const uint32_t* a, const uint32_t* b) {
    asm volatile("mma.sync.aligned.m16n8k16.row.col.f32.bf16.bf16.f32 "
        "{%0,%1,%2,%3}, {%4,%5,%6,%7}, {%8,%9}, {%0,%1,%2,%3};"
        : "+f"(d[0]), "+f"(d[1]), "+f"(d[2]), "+f"(d[3])
        : "r"(a[0]), "r"(a[1]), "r"(a[2]), "r"(a[3]), "r"(b[0]), "r"(b[1]));
}

// ------------------------- init / prep -----------------------------------------
__global__ void init_kernel() {
    int i = blockIdx.x*blockDim.x + threadIdx.x;
    if (i < 2*BB*DD) g_hstate[i] = 0.f;
    if (i < 8) g_cnt[i] = 0u;
}

__global__ void prep_w(const float* __restrict__ W, bf16* __restrict__ Wh,
                       bf16* __restrict__ Wl, int N, int K, int Np, int Kp) {
    size_t i = (size_t)blockIdx.x*256 + threadIdx.x;
    if (i >= (size_t)Np*Kp) return;
    int n = (int)(i / Kp), k = (int)(i % Kp);
    float v = (n < N && k < K) ? W[(size_t)n*K + k] : 0.f;
    bf16 h = __float2bfloat16(v);
    Wh[i] = h;
    Wl[i] = __float2bfloat16(v - __bfloat162float(h));
}

__global__ void prep_upb(const float* __restrict__ b) {
    int i = blockIdx.x*blockDim.x + threadIdx.x;
    if (i < UPAD) g_upb[i] = (i < 2*UU) ? b[i] : 0.f;
}

// ------------------------- LayerNorm -> bf16 hi/lo planes ----------------------
__global__ __launch_bounds__(256) void ln_kernel(const float* __restrict__ x,
                                                 const float* __restrict__ w,
                                                 const float* __restrict__ b) {
    int m = blockIdx.x, tid = threadIdx.x;
    const float* row = x + (size_t)m*DD;
    float4 v = *(const float4*)&row[tid*4];
    float s = v.x+v.y+v.z+v.w;
    float ss = v.x*v.x+v.y*v.y+v.z*v.z+v.w*v.w;
    __shared__ float rs[8], rss[8];
    #pragma unroll
    for (int o=16;o>0;o>>=1){ s+=__shfl_down_sync(0xffffffffu,s,o); ss+=__shfl_down_sync(0xffffffffu,ss,o); }
    if ((tid&31)==0){ rs[tid>>5]=s; rss[tid>>5]=ss; }
    __syncthreads();
    float ts=0.f, tss=0.f;
    #pragma unroll
    for (int wp=0;wp<8;wp++){ ts+=rs[wp]; tss+=rss[wp]; }
    float mu = ts*(1.0f/DD);
    float inv = rsqrtf(tss*(1.0f/DD) - mu*mu + 1e-5f);
    int d = tid*4;
    size_t o0 = (size_t)m*DD + d;
    float ov[4] = {(v.x-mu)*inv*w[d+0]+b[d+0], (v.y-mu)*inv*w[d+1]+b[d+1],
                   (v.z-mu)*inv*w[d+2]+b[d+2], (v.w-mu)*inv*w[d+3]+b[d+3]};
    #pragma unroll
    for (int q=0;q<4;q++){
        bf16 h = __float2bfloat16(ov[q]);
        g_xn_h[o0+q] = h;
        g_xn_l[o0+q] = __float2bfloat16(ov[q] - __bfloat162float(h));
    }
}

// ------------------------- causal conv K=4 + swish -> planes -------------------
__global__ __launch_bounds__(256) void conv_kernel(const float* __restrict__ cw,
                                                   const float* __restrict__ cb) {
    size_t idx = (size_t)blockIdx.x*blockDim.x + threadIdx.x;
    int d = (int)(idx & (DD-1));
    int t = (int)((idx >> 10) & (TT-1));
    float4 c4 = *(const float4*)&cw[d*4];
    float x0 = __bfloat162float(g_xn_h[idx]) + __bfloat162float(g_xn_l[idx]);
    float acc = cb[d] + c4.w * x0;
    if (t>=1) acc += c4.z * (__bfloat162float(g_xn_h[idx-DD])   + __bfloat162float(g_xn_l[idx-DD]));
    if (t>=2) acc += c4.y * (__bfloat162float(g_xn_h[idx-2*DD]) + __bfloat162float(g_xn_l[idx-2*DD]));
    if (t>=3) acc += c4.x * (__bfloat162float(g_xn_h[idx-3*DD]) + __bfloat162float(g_xn_l[idx-3*DD]));
    float v = acc / (1.0f + expf(-acc));
    bf16 h = __float2bfloat16(v);
    g_if_h[idx] = h;
    g_if_l[idx] = __float2bfloat16(v - __bfloat162float(h));
}

// ------------------------- mma.sync split-bf16 GEMM ----------------------------
// C[M,N] = (Ah+Al)[M,Kp] @ (Bh+Bl)[N,Kp]^T, fp32 out.
// CTA tile 128x128, Kchunk 64, double-buffered cp.async, 8 warps (4m x 2n),
// warp tile 32x64. EPI: 0 none, 1 +bias, 2 +bias+res.
#define GSTG 65536            // stage = 4 sub-tiles of 128x64 bf16 (16KB each)
#define GEMM_SMEM 131072

template<int EPI>
__global__ __launch_bounds__(256, 1) void gemm_mma(const bf16* __restrict__ Ah,
                                                   const bf16* __restrict__ Al,
                                                   const bf16* __restrict__ Bh,
                                                   const bf16* __restrict__ Bl,
                                                   float* __restrict__ C,
                                                   const float* __restrict__ bias,
                                                   const float* __restrict__ res,
                                                   int Kp, int nch, int ldc) {
    extern __shared__ __align__(128) char smem[];
    uint32_t sbase = (uint32_t)__cvta_generic_to_shared(smem);
    int tid = threadIdx.x, wid = tid >> 5, lane = tid & 31;
    size_t bm = (size_t)blockIdx.y * 128;
    size_t bn = (size_t)blockIdx.x * 128;
    const bf16* pAh = Ah + bm*(size_t)Kp;
    const bf16* pAl = Al + bm*(size_t)Kp;
    const bf16* pBh = Bh + bn*(size_t)Kp;
    const bf16* pBl = Bl + bn*(size_t)Kp;

    int row0 = tid >> 3, c16 = tid & 7;
    auto ld_tile = [&](const bf16* src, uint32_t dstb, int kc) {
        #pragma unroll
        for (int ii = 0; ii < 4; ii++) {
            int row = row0 + ii*32;
            cp_async16(dstb + sw128((uint32_t)(row*128 + c16*16)),
                       src + (size_t)row*Kp + kc*64 + c16*8);
        }
    };
    auto load_chunk = [&](int kc, int st) {
        uint32_t tb = sbase + st*GSTG;
        ld_tile(pAh, tb,         kc);
        ld_tile(pAl, tb + 16384, kc);
        ld_tile(pBh, tb + 32768, kc);
        ld_tile(pBl, tb + 49152, kc);
    };

    int wm = wid & 3, wn = wid >> 2;           // warp tile: rows wm*32, cols wn*64
    int lsub = lane >> 3, lr = lane & 7;

    float acc[2][8][4];
    #pragma unroll
    for (int mi=0;mi<2;mi++)
        #pragma unroll
        for (int ni=0;ni<8;ni++)
            #pragma unroll
            for (int q=0;q<4;q++) acc[mi][ni][q] = 0.f;

    load_chunk(0, 0);
    cp_commit();

    for (int k = 0; k < nch; k++) {
        int st = k & 1;
        if (k+1 < nch) { load_chunk(k+1, st^1); cp_commit(); cp_wait<1>(); }
        else           { cp_wait<0>(); }
        __syncthreads();

        uint32_t tb = sbase + st*GSTG;
        uint32_t aH = tb, aL = tb + 16384, bH = tb + 32768, bL = tb + 49152;

        #pragma unroll
        for (int kk = 0; kk < 4; kk++) {
            int k0 = kk*16;
            uint32_t afh[2][4], afl[2][4];
            #pragma unroll
            for (int mi = 0; mi < 2; mi++) {
                int row = wm*32 + mi*16 + (lsub & 1)*8 + lr;
                int kb  = k0 + (lsub >> 1)*8;
                uint32_t off = sw128((uint32_t)(row*128 + kb*2));
                ldm_x4(afh[mi], aH + off);
                ldm_x4(afl[mi], aL + off);
            }
            uint32_t bfh[8][2], bfl[8][2];
            #pragma unroll
            for (int np = 0; np < 4; np++) {
                int n  = wn*64 + np*16 + (lsub >> 1)*8 + lr;
                int kb = k0 + (lsub & 1)*8;
                uint32_t off = sw128((uint32_t)(n*128 + kb*2));
                uint32_t r4[4];
                ldm_x4(r4, bH + off);
                bfh[np*2][0]=r4[0]; bfh[np*2][1]=r4[1]; bfh[np*2+1][0]=r4[2]; bfh[np*2+1][1]=r4[3];
                ldm_x4(r4, bL + off);
                bfl[np*2][0]=r4[0]; bfl[np*2][1]=r4[1]; bfl[np*2+1][0]=r4[2]; bfl[np*2+1][1]=r4[3];
            }
            #pragma unroll
            for (int mi = 0; mi < 2; mi++)
                #pragma unroll
                for (int ni = 0; ni < 8; ni++) {
                    mma_bf16(acc[mi][ni], afh[mi], bfh[ni]);
                    mma_bf16(acc[mi][ni], afh[mi], bfl[ni]);
                    mma_bf16(acc[mi][ni], afl[mi], bfh[ni]);
                }
        }
        __syncthreads();
    }

    // epilogue: direct stores
    int g = lane >> 2, tg = lane & 3;
    #pragma unroll
    for (int mi = 0; mi < 2; mi++) {
        size_t r0 = bm + wm*32 + mi*16 + g;
        size_t r1 = r0 + 8;
        #pragma unroll
        for (int ni = 0; ni < 8; ni++) {
            int col = (int)bn + wn*64 + ni*8 + tg*2;
            float b0 = 0.f, b1 = 0.f;
            if (EPI >= 1) { b0 = bias[col]; b1 = bias[col+1]; }
            float d0 = acc[mi][ni][0] + b0;
            float d1 = acc[mi][ni][1] + b1;
            float d2 = acc[mi][ni][2] + b0;
            float d3 = acc[mi][ni][3] + b1;
            if (EPI == 2) {
                const float* rr0 = res + r0*(size_t)ldc + col;
                const float* rr1 = res + r1*(size_t)ldc + col;
                d0 += rr0[0]; d1 += rr0[1]; d2 += rr1[0]; d3 += rr1[1];
            }
            *(float2*)&C[r0*(size_t)ldc + col] = make_float2(d0, d1);
            *(float2*)&C[r1*(size_t)ldc + col] = make_float2(d2, d3);
        }
    }
}

// ------------------------- sequential sLSTM recurrence (64 CTAs) ---------------
__global__ __launch_bounds__(256) void recur_kernel(const float* __restrict__ w_hh,
                                                    const float* __restrict__ bias) {
    extern __shared__ float sm[];
    float* Wsm    = sm;                 // 128 * 260
    float* h_sm   = Wsm + 128*260;      // 4 * 256
    float* lin_sm = h_sm + 1024;        // 128 * 4

    int tid  = threadIdx.x;
    int head = blockIdx.x >> 4;
    int j    = (blockIdx.x >> 1) & 7;
    int bg   = blockIdx.x & 1;
    int r  = tid & 127;
    int bq = tid >> 7;
    int g  = r >> 5, sl = r & 31;

    #pragma unroll
    for (int it = 0; it < 32; ++it) {
        int idx4 = tid + it*256;
        int rl = idx4 >> 6;
        int k4 = (idx4 & 63) << 2;
        int gg = rl >> 5, ssl = rl & 31;
        float4 wv = *(const float4*)&w_hh[((size_t)(head*1024 + gg*256 + j*32 + ssl))*256 + k4];
        *(float4*)&Wsm[rl*260 + k4] = wv;
    }

    float bias_v = bias[head*1024 + g*256 + j*32 + sl];
    const float* linp = (g < 2) ? g_linif : g_linzo;
    size_t colOff = (size_t)head*512 + (size_t)(g & 1)*256 + j*32 + sl;
    int b0 = bg*4 + bq*2;

    int gs = tid & 31;
    int gb = tid >> 5;
    float c_st = 0.f, m_st = 0.f, n_st = 0.f;
    int cidx = head*2 + bg;
    __syncthreads();

    int p = 0;
    for (int t = 0; t < TT; ++t) {
        float l0 = linp[((size_t)(b0+0)*TT + t)*2048 + colOff];
        float l1 = linp[((size_t)(b0+1)*TT + t)*2048 + colOff];

        const float* hp = g_hstate + p*BB*DD;
        {
            int bb = tid >> 6;
            int kk = (tid & 63) << 2;
            float4 hv = __ldcg((const float4*)&hp[(bg*4+bb)*DD + head*256 + kk]);
            *(float4*)&h_sm[bb*256 + kk] = hv;
        }
        __syncthreads();

        float a0 = l0 + bias_v, a1 = l1 + bias_v;
        const float* w  = &Wsm[r*260];
        const float* hA = &h_sm[(bq*2)*256];
        #pragma unroll 8
        for (int k = 0; k < 256; k += 4) {
            float4 wv = *(const float4*)(w+k);
            float4 x0 = *(const float4*)(hA + k);
            float4 x1 = *(const float4*)(hA + 256 + k);
            a0 += wv.x*x0.x + wv.y*x0.y + wv.z*x0.z + wv.w*x0.w;
            a1 += wv.x*x1.x + wv.y*x1.y + wv.z*x1.z + wv.w*x1.w;
        }
        lin_sm[r*4 + bq*2 + 0] = a0;
        lin_sm[r*4 + bq*2 + 1] = a1;
        __syncthreads();

        if (tid < 128) {
            float iv = lin_sm[gs*4 + gb];
            float fv = lin_sm[(32+gs)*4 + gb];
            float zv = tanhf(lin_sm[(64+gs)*4 + gb]);
            float ov = 1.0f/(1.0f + expf(-lin_sm[(96+gs)*4 + gb]));
            float mn = fmaxf(fv + m_st, iv);
            float ie = expf(iv - mn);
            float fe = expf(fv + m_st - mn);
            c_st = fe*c_st + ie*zv;
            n_st = fe*n_st + ie;
            m_st = mn;
            float hn = ov * (c_st / n_st);
            int sg = j*32 + gs;
            int b  = bg*4 + gb;
            __stcg(&g_hstate[(p^1)*BB*DD + b*DD + head*256 + sg], hn);
            g_hall[((size_t)b*TT + t)*DD + head*256 + sg] = hn;
        }

        __threadfence();
        __syncthreads();
        if (tid == 0) {
            atomicAdd(&g_cnt[cidx], 1u);
            volatile unsigned* cv = &g_cnt[cidx];
            unsigned tgt = 8u*(unsigned)(t+1);
            while (*cv < tgt) {}
            __threadfence();
        }
        __syncthreads();
        p ^= 1;
    }
}

// ------------------------- GroupNorm -> bf16 planes ----------------------------
__global__ __launch_bounds__(256) void gn_kernel(const float* __restrict__ w,
                                                 const float* __restrict__ b) {
    int m = blockIdx.x, tid = threadIdx.x;
    const float* row = g_hall + (size_t)m*DD;
    float4 v = *(const float4*)&row[tid*4];
    float s = v.x+v.y+v.z+v.w;
    float ss = v.x*v.x+v.y*v.y+v.z*v.z+v.w*v.w;
    __shared__ float ws[8], wss[8];
    #pragma unroll
    for (int o=16;o>0;o>>=1){ s+=__shfl_down_sync(0xffffffffu,s,o); ss+=__shfl_down_sync(0xffffffffu,ss,o); }
    if ((tid&31)==0){ ws[tid>>5]=s; wss[tid>>5]=ss; }
    __syncthreads();
    int h = tid >> 6;
    float hs  = ws[2*h]  + ws[2*h+1];
    float hss = wss[2*h] + wss[2*h+1];
    float mu = hs*(1.0f/256.0f);
    float inv = rsqrtf(hss*(1.0f/256.0f) - mu*mu + 1e-5f);
    int d = tid*4;
    size_t o0 = (size_t)m*DD + d;
    float ov[4] = {(v.x-mu)*inv*w[d+0]+b[d+0], (v.y-mu)*inv*w[d+1]+b[d+1],
                   (v.z-mu)*inv*w[d+2]+b[d+2], (v.w-mu)*inv*w[d+3]+b[d+3]};
    #pragma unroll
    for (int q=0;q<4;q++){
        bf16 hh = __float2bfloat16(ov[q]);
        g_zn_h[o0+q] = hh;
        g_zn_l[o0+q] = __float2bfloat16(ov[q] - __bfloat162float(hh));
    }
}

// ------------------------- gelu(u1)*u2 -> bf16 planes (K-padded) ---------------
__global__ __launch_bounds__(256) void act_kernel() {
    int m = blockIdx.x;
    const float* up = g_up + (size_t)m*UPAD;
    size_t o = (size_t)m*KDN;
    for (int c = threadIdx.x; c < KDN; c += 256) {
        float v = 0.f;
        if (c < UU) {
            float u1 = up[c], u2 = up[UU + c];
            float gl = 0.5f*u1*(1.0f + tanhf(0.7978845608028654f*(u1 + 0.044715f*u1*u1*u1)));
            v = gl * u2;
        }
        bf16 h = __float2bfloat16(v);
        g_act_h[o+c] = h;
        g_act_l[o+c] = __float2bfloat16(v - __bfloat162float(h));
    }
}

// ------------------------- launch ----------------------------------------------
extern "C" void kernel_launch(void* const* d_in, const int* in_sizes, int n_in,
                              void* d_out, int out_size) {
    const float* x      = (const float*)d_in[0];
    const float* ln_w   = (const float*)d_in[1];
    const float* ln_b   = (const float*)d_in[2];
    const float* conv_w = (const float*)d_in[3];
    const float* conv_b = (const float*)d_in[4];
    const float* w_if   = (const float*)d_in[5];
    const float* w_zo   = (const float*)d_in[6];
    const float* w_hh   = (const float*)d_in[7];
    const float* bias   = (const float*)d_in[8];
    const float* gn_w   = (const float*)d_in[9];
    const float* gn_b   = (const float*)d_in[10];
    const float* up_w   = (const float*)d_in[11];
    const float* up_b   = (const float*)d_in[12];
    const float* dn_w   = (const float*)d_in[13];
    const float* dn_b   = (const float*)d_in[14];
    float* out = (float*)d_out;

    bf16 *p_xnh,*p_xnl,*p_ifh,*p_ifl,*p_znh,*p_znl,*p_ach,*p_acl;
    bf16 *p_wifh,*p_wifl,*p_wzoh,*p_wzol,*p_wuph,*p_wupl,*p_wdnh,*p_wdnl;
    float *p_linif,*p_linzo,*p_up,*p_upb;
    cudaGetSymbolAddress((void**)&p_xnh, g_xn_h);   cudaGetSymbolAddress((void**)&p_xnl, g_xn_l);
    cudaGetSymbolAddress((void**)&p_ifh, g_if_h);   cudaGetSymbolAddress((void**)&p_ifl, g_if_l);
    cudaGetSymbolAddress((void**)&p_znh, g_zn_h);   cudaGetSymbolAddress((void**)&p_znl, g_zn_l);
    cudaGetSymbolAddress((void**)&p_ach, g_act_h);  cudaGetSymbolAddress((void**)&p_acl, g_act_l);
    cudaGetSymbolAddress((void**)&p_wifh, g_wif_h); cudaGetSymbolAddress((void**)&p_wifl, g_wif_l);
    cudaGetSymbolAddress((void**)&p_wzoh, g_wzo_h); cudaGetSymbolAddress((void**)&p_wzol, g_wzo_l);
    cudaGetSymbolAddress((void**)&p_wuph, g_wup_h); cudaGetSymbolAddress((void**)&p_wupl, g_wup_l);
    cudaGetSymbolAddress((void**)&p_wdnh, g_wdn_h); cudaGetSymbolAddress((void**)&p_wdnl, g_wdn_l);
    cudaGetSymbolAddress((void**)&p_linif, g_linif);
    cudaGetSymbolAddress((void**)&p_linzo, g_linzo);
    cudaGetSymbolAddress((void**)&p_up, g_up);
    cudaGetSymbolAddress((void**)&p_upb, g_upb);

    cudaFuncSetAttribute(gemm_mma<0>, cudaFuncAttributeMaxDynamicSharedMemorySize, GEMM_SMEM);
    cudaFuncSetAttribute(gemm_mma<1>, cudaFuncAttributeMaxDynamicSharedMemorySize, GEMM_SMEM);
    cudaFuncSetAttribute(gemm_mma<2>, cudaFuncAttributeMaxDynamicSharedMemorySize, GEMM_SMEM);
    const int RECUR_SMEM = (128*260 + 1024 + 512) * 4;
    cudaFuncSetAttribute(recur_kernel, cudaFuncAttributeMaxDynamicSharedMemorySize, RECUR_SMEM);

    init_kernel<<<64, 256>>>();
    prep_w<<<(2048*1024 + 255)/256, 256>>>(w_if, p_wifh, p_wifl, 2048, 1024, 2048, 1024);
    prep_w<<<(2048*1024 + 255)/256, 256>>>(w_zo, p_wzoh, p_wzol, 2048, 1024, 2048, 1024);
    prep_w<<<(UPAD*1024 + 255)/256, 256>>>(up_w, p_wuph, p_wupl, 2*UU, 1024, UPAD, 1024);
    prep_w<<<(1024*KDN + 255)/256, 256>>>(dn_w, p_wdnh, p_wdnl, 1024, UU, 1024, KDN);
    prep_upb<<<(UPAD + 255)/256, 256>>>(up_b);

    ln_kernel<<<BT, 256>>>(x, ln_w, ln_b);
    conv_kernel<<<(int)(((size_t)BT*DD)/256), 256>>>(conv_w, conv_b);

    gemm_mma<0><<<dim3(16, 128), 256, GEMM_SMEM>>>(p_ifh, p_ifl, p_wifh, p_wifl,
        p_linif, nullptr, nullptr, 1024, 16, 2048);
    gemm_mma<0><<<dim3(16, 128), 256, GEMM_SMEM>>>(p_xnh, p_xnl, p_wzoh, p_wzol,
        p_linzo, nullptr, nullptr, 1024, 16, 2048);

    recur_kernel<<<64, 256, RECUR_SMEM>>>(w_hh, bias);

    gn_kernel<<<BT, 256>>>(gn_w, gn_b);

    gemm_mma<1><<<dim3(22, 128), 256, GEMM_SMEM>>>(p_znh, p_znl, p_wuph, p_wupl,
        p_up, p_upb, nullptr, 1024, 16, UPAD);

    act_kernel<<<BT, 256>>>();

    gemm_mma<2><<<dim3(8, 128), 256, GEMM_SMEM>>>(p_ach, p_acl, p_wdnh, p_wdnl,
        out, dn_b, x, KDN, 22, 1024);
}